// round 1
// baseline (speedup 1.0000x reference)
#include <cuda_runtime.h>
#include <cuda_bf16.h>

#define BB   16
#define CIN  128
#define COUT 128
#define HH   64
#define WW   64
#define KK   9
#define CCHUNK 16

// Scratch: weight transposed to [k][c][o] for coalesced staging (no allocs allowed).
__device__ float g_Wt[KK * CIN * COUT];

__global__ void prep_weights_kernel(const float* __restrict__ w) {
    int idx = blockIdx.x * blockDim.x + threadIdx.x;   // over COUT*CIN*KK
    if (idx >= COUT * CIN * KK) return;
    int k = idx % KK;
    int c = (idx / KK) % CIN;
    int o = idx / (KK * CIN);
    g_Wt[(k * CIN + c) * COUT + o] = w[idx];
}

union F2U {
    float2 f;
    unsigned long long u;
};

#define FMA2(acc, a, b) \
    asm("fma.rn.f32x2 %0, %1, %2, %0;" : "+l"((acc).u) : "l"((a).u), "l"((b).u))

__global__ __launch_bounds__(256, 2)
void lmconv_kernel(const float* __restrict__ x,
                   const float* __restrict__ mask,
                   const float* __restrict__ mw,
                   const float* __restrict__ bias,
                   float* __restrict__ out)
{
    __shared__ float  maskS[KK][WW];           // 2304 B
    __shared__ float2 Wd[CCHUNK][COUT];        // 16 KB (duplicated weight pairs)
    __shared__ float  Xs[CCHUNK][WW];          // 4 KB (masked, shifted input)

    const int h   = blockIdx.x;                // output row
    const int b   = blockIdx.y;                // batch
    const int tid = threadIdx.x;
    const int ty  = tid >> 4;                  // 0..15 : cout group (8 couts)
    const int tx  = tid & 15;                  // 0..15 : pixel group (4 pixels)

    // ---- load mask row for all 9 taps ----
    #pragma unroll
    for (int i = tid; i < KK * WW; i += 256) {
        int k = i >> 6, w = i & 63;
        maskS[k][w] = mask[k * (HH * WW) + h * WW + w];
    }
    __syncthreads();

    // ---- init accumulators with bias + mask_weight term ----
    F2U acc2[8][2];
    #pragma unroll
    for (int o = 0; o < 8; o++) {
        int oo = ty * 8 + o;
        float bv = bias[oo];
        float s0 = bv, s1 = bv, s2 = bv, s3 = bv;
        #pragma unroll
        for (int k = 0; k < KK; k++) {
            float m = mw[oo * KK + k];
            s0 += m * maskS[k][tx * 4 + 0];
            s1 += m * maskS[k][tx * 4 + 1];
            s2 += m * maskS[k][tx * 4 + 2];
            s3 += m * maskS[k][tx * 4 + 3];
        }
        acc2[o][0].f = make_float2(s0, s1);
        acc2[o][1].f = make_float2(s2, s3);
    }

    const float* xb = x + (size_t)b * CIN * HH * WW;

    // ---- mainloop: cin chunks x 9 taps, accumulate one GEMM ----
    for (int cc = 0; cc < CIN; cc += CCHUNK) {
        #pragma unroll 1
        for (int k = 0; k < KK; k++) {
            const int dy = k / 3 - 1;
            const int dx = k % 3 - 1;
            const int sr = h + dy;
            const bool rowok = ((unsigned)sr < HH);

            // stage masked, shifted input: Xs[c][w] = x[c, h+dy, w+dx] * mask[k, h, w]
            #pragma unroll
            for (int i = tid; i < CCHUNK * WW; i += 256) {
                int c = i >> 6, w = i & 63;
                int sc = w + dx;
                float v = 0.0f;
                if (rowok && (unsigned)sc < WW)
                    v = xb[((size_t)(cc + c) * HH + sr) * WW + sc] * maskS[k][w];
                Xs[c][w] = v;
            }

            // stage duplicated weight pairs: Wd[c][o] = (W[o,c,k], W[o,c,k])
            const float* wk = g_Wt + (k * CIN + cc) * COUT;
            #pragma unroll
            for (int i = tid; i < CCHUNK * COUT; i += 256) {
                int c = i >> 7, o = i & 127;
                float wv = wk[c * COUT + o];
                Wd[c][o] = make_float2(wv, wv);
            }
            __syncthreads();

            // compute: 16 cin x (8 couts x 4 pixels) with packed f32x2 FMA
            #pragma unroll
            for (int c = 0; c < CCHUNK; c++) {
                float4 xv = *reinterpret_cast<const float4*>(&Xs[c][tx * 4]);
                F2U xp0, xp1;
                xp0.f = make_float2(xv.x, xv.y);
                xp1.f = make_float2(xv.z, xv.w);
                const float4* wrow =
                    reinterpret_cast<const float4*>(&Wd[c][ty * 8]);
                #pragma unroll
                for (int j = 0; j < 4; j++) {
                    float4 wv = wrow[j];        // two duplicated pairs
                    F2U wa, wb;
                    wa.f = make_float2(wv.x, wv.y);
                    wb.f = make_float2(wv.z, wv.w);
                    FMA2(acc2[2 * j + 0][0], wa, xp0);
                    FMA2(acc2[2 * j + 0][1], wa, xp1);
                    FMA2(acc2[2 * j + 1][0], wb, xp0);
                    FMA2(acc2[2 * j + 1][1], wb, xp1);
                }
            }
            __syncthreads();
        }
    }

    // ---- store: out[b][o][h][w], float4 per cout ----
    #pragma unroll
    for (int o = 0; o < 8; o++) {
        int oo = ty * 8 + o;
        float4 r;
        r.x = acc2[o][0].f.x;
        r.y = acc2[o][0].f.y;
        r.z = acc2[o][1].f.x;
        r.w = acc2[o][1].f.y;
        *reinterpret_cast<float4*>(
            &out[(((size_t)b * COUT + oo) * HH + h) * WW + tx * 4]) = r;
    }
}

extern "C" void kernel_launch(void* const* d_in, const int* in_sizes, int n_in,
                              void* d_out, int out_size) {
    const float* x    = (const float*)d_in[0];   // (16,128,64,64)
    const float* mask = (const float*)d_in[1];   // (1,9,4096)
    const float* w    = (const float*)d_in[2];   // (128,128,3,3)
    const float* mw   = (const float*)d_in[3];   // (128,3,3)
    const float* bias = (const float*)d_in[4];   // (128,)
    float* out = (float*)d_out;                  // (16,128,64,64)

    prep_weights_kernel<<<(COUT * CIN * KK + 255) / 256, 256>>>(w);

    dim3 grid(HH, BB);
    lmconv_kernel<<<grid, 256>>>(x, mask, mw, bias, out);
}

// round 2
// speedup vs baseline: 1.0029x; 1.0029x over previous
#include <cuda_runtime.h>
#include <cuda_bf16.h>

#define BB   16
#define CIN  128
#define COUT 128
#define HH   64
#define WW   64
#define KK   9
#define CCHUNK 16

// Scratch: weight transposed to [k][c][o] for coalesced staging (no allocs allowed).
__device__ float g_Wt[KK * CIN * COUT];

__global__ void prep_weights_kernel(const float* __restrict__ w) {
    int idx = blockIdx.x * blockDim.x + threadIdx.x;   // over COUT*CIN*KK
    if (idx >= COUT * CIN * KK) return;
    int k = idx % KK;
    int c = (idx / KK) % CIN;
    int o = idx / (KK * CIN);
    g_Wt[(k * CIN + c) * COUT + o] = w[idx];
}

union F2U {
    float2 f;
    unsigned long long u;
};

#define FMA2(acc, a, b) \
    asm("fma.rn.f32x2 %0, %1, %2, %0;" : "+l"((acc).u) : "l"((a).u), "l"((b).u))

__global__ __launch_bounds__(256, 2)
void lmconv_kernel(const float* __restrict__ x,
                   const float* __restrict__ mask,
                   const float* __restrict__ mw,
                   const float* __restrict__ bias,
                   float* __restrict__ out)
{
    __shared__ float  maskS[KK][WW];           // 2304 B
    __shared__ float2 Wd[CCHUNK][COUT];        // 16 KB (duplicated weight pairs)
    __shared__ float  Xs[CCHUNK][WW];          // 4 KB (masked, shifted input)

    const int h   = blockIdx.x;                // output row
    const int b   = blockIdx.y;                // batch
    const int tid = threadIdx.x;
    const int ty  = tid >> 4;                  // 0..15 : cout group (8 couts)
    const int tx  = tid & 15;                  // 0..15 : pixel group (4 pixels)

    // ---- load mask row for all 9 taps ----
    #pragma unroll
    for (int i = tid; i < KK * WW; i += 256) {
        int k = i >> 6, w = i & 63;
        maskS[k][w] = mask[k * (HH * WW) + h * WW + w];
    }
    __syncthreads();

    // ---- init accumulators with bias + mask_weight term ----
    F2U acc2[8][2];
    #pragma unroll
    for (int o = 0; o < 8; o++) {
        int oo = ty * 8 + o;
        float bv = bias[oo];
        float s0 = bv, s1 = bv, s2 = bv, s3 = bv;
        #pragma unroll
        for (int k = 0; k < KK; k++) {
            float m = mw[oo * KK + k];
            s0 += m * maskS[k][tx * 4 + 0];
            s1 += m * maskS[k][tx * 4 + 1];
            s2 += m * maskS[k][tx * 4 + 2];
            s3 += m * maskS[k][tx * 4 + 3];
        }
        acc2[o][0].f = make_float2(s0, s1);
        acc2[o][1].f = make_float2(s2, s3);
    }

    const float* xb = x + (size_t)b * CIN * HH * WW;

    // ---- mainloop: cin chunks x 9 taps, accumulate one GEMM ----
    for (int cc = 0; cc < CIN; cc += CCHUNK) {
        #pragma unroll 1
        for (int k = 0; k < KK; k++) {
            const int dy = k / 3 - 1;
            const int dx = k % 3 - 1;
            const int sr = h + dy;
            const bool rowok = ((unsigned)sr < HH);

            // stage masked, shifted input: Xs[c][w] = x[c, h+dy, w+dx] * mask[k, h, w]
            #pragma unroll
            for (int i = tid; i < CCHUNK * WW; i += 256) {
                int c = i >> 6, w = i & 63;
                int sc = w + dx;
                float v = 0.0f;
                if (rowok && (unsigned)sc < WW)
                    v = xb[((size_t)(cc + c) * HH + sr) * WW + sc] * maskS[k][w];
                Xs[c][w] = v;
            }

            // stage duplicated weight pairs: Wd[c][o] = (W[o,c,k], W[o,c,k])
            const float* wk = g_Wt + (k * CIN + cc) * COUT;
            #pragma unroll
            for (int i = tid; i < CCHUNK * COUT; i += 256) {
                int c = i >> 7, o = i & 127;
                float wv = wk[c * COUT + o];
                Wd[c][o] = make_float2(wv, wv);
            }
            __syncthreads();

            // compute: 16 cin x (8 couts x 4 pixels) with packed f32x2 FMA
            #pragma unroll
            for (int c = 0; c < CCHUNK; c++) {
                float4 xv = *reinterpret_cast<const float4*>(&Xs[c][tx * 4]);
                F2U xp0, xp1;
                xp0.f = make_float2(xv.x, xv.y);
                xp1.f = make_float2(xv.z, xv.w);
                const float4* wrow =
                    reinterpret_cast<const float4*>(&Wd[c][ty * 8]);
                #pragma unroll
                for (int j = 0; j < 4; j++) {
                    float4 wv = wrow[j];        // two duplicated pairs
                    F2U wa, wb;
                    wa.f = make_float2(wv.x, wv.y);
                    wb.f = make_float2(wv.z, wv.w);
                    FMA2(acc2[2 * j + 0][0], wa, xp0);
                    FMA2(acc2[2 * j + 0][1], wa, xp1);
                    FMA2(acc2[2 * j + 1][0], wb, xp0);
                    FMA2(acc2[2 * j + 1][1], wb, xp1);
                }
            }
            __syncthreads();
        }
    }

    // ---- store: out[b][o][h][w], float4 per cout ----
    #pragma unroll
    for (int o = 0; o < 8; o++) {
        int oo = ty * 8 + o;
        float4 r;
        r.x = acc2[o][0].f.x;
        r.y = acc2[o][0].f.y;
        r.z = acc2[o][1].f.x;
        r.w = acc2[o][1].f.y;
        *reinterpret_cast<float4*>(
            &out[(((size_t)b * COUT + oo) * HH + h) * WW + tx * 4]) = r;
    }
}

extern "C" void kernel_launch(void* const* d_in, const int* in_sizes, int n_in,
                              void* d_out, int out_size) {
    const float* x    = (const float*)d_in[0];   // (16,128,64,64)
    const float* mask = (const float*)d_in[1];   // (1,9,4096)
    const float* w    = (const float*)d_in[2];   // (128,128,3,3)
    const float* mw   = (const float*)d_in[3];   // (128,3,3)
    const float* bias = (const float*)d_in[4];   // (128,)
    float* out = (float*)d_out;                  // (16,128,64,64)

    prep_weights_kernel<<<(COUT * CIN * KK + 255) / 256, 256>>>(w);

    dim3 grid(HH, BB);
    lmconv_kernel<<<grid, 256>>>(x, mask, mw, bias, out);
}

// round 4
// speedup vs baseline: 2.0674x; 2.0615x over previous
#include <cuda_runtime.h>
#include <cuda_fp16.h>

#define BB      16
#define CINW    128
#define COUTW   128
#define LPIX    4096
#define KTAP    9
#define XT_ROWS 4352            // 128 zero-pad + 4096 + 128 zero-pad
#define TILE_N  128
#define NTILES  32              // 4096/128

// smem stage layout: rows padded to 72 halfs (144B) for conflict-free ldmatrix
#define ROWB    144
#define TILEB   (128 * ROWB)    // 18432
#define OFF_AH  0
#define OFF_AL  (1 * TILEB)
#define OFF_BH  (2 * TILEB)
#define OFF_BL  (3 * TILEB)
#define STAGE_BYTES (4 * TILEB) // 73728
#define SM_MASK 0               // 9*128 u32 = 4608
#define SM_BUF  4608
#define SMEM_TOTAL (SM_BUF + 2 * STAGE_BYTES)   // 152064

// ---- global scratch (__device__ arrays: allocation-free rule) ----
__device__ __align__(16) __half g_xh[(size_t)BB * XT_ROWS * CINW];
__device__ __align__(16) __half g_xl[(size_t)BB * XT_ROWS * CINW];
__device__ __align__(16) __half g_ah[KTAP * 2 * 128 * 64];   // [(k,ch)][o][c] compact
__device__ __align__(16) __half g_al[KTAP * 2 * 128 * 64];
__device__ __align__(16) float  g_mterm[(size_t)COUTW * LPIX];

// ================= PTX helpers (baseline ISA only) =================
__device__ __forceinline__ unsigned smem_u32(const void* p) {
    unsigned a;
    asm("{ .reg .u64 t; cvta.to.shared.u64 t, %1; cvt.u32.u64 %0, t; }" : "=r"(a) : "l"(p));
    return a;
}
__device__ __forceinline__ void ldsm4(unsigned* r, unsigned addr) {
    asm volatile("ldmatrix.sync.aligned.m8n8.x4.shared.b16 {%0,%1,%2,%3}, [%4];"
                 : "=r"(r[0]), "=r"(r[1]), "=r"(r[2]), "=r"(r[3]) : "r"(addr));
}
__device__ __forceinline__ void mma16816(float* c, const unsigned* a,
                                         unsigned b0, unsigned b1) {
    asm volatile(
        "mma.sync.aligned.m16n8k16.row.col.f32.f16.f16.f32 "
        "{%0,%1,%2,%3}, {%4,%5,%6,%7}, {%8,%9}, {%0,%1,%2,%3};"
        : "+f"(c[0]), "+f"(c[1]), "+f"(c[2]), "+f"(c[3])
        : "r"(a[0]), "r"(a[1]), "r"(a[2]), "r"(a[3]), "r"(b0), "r"(b1));
}

// ================= prep kernels =================
// x[b][c][l] fp32 -> x_t[b][128+l][c] fp16 hi/lo via smem tile transpose
__global__ void prep_x_kernel(const float* __restrict__ x) {
    __shared__ float sm[32][33];
    int b = blockIdx.z, cg = blockIdx.y, lg = blockIdx.x;
    int tid = threadIdx.x;
    int lr = tid & 31, cr = tid >> 5;
    #pragma unroll
    for (int r = 0; r < 4; r++) {
        int c = cg * 32 + cr + r * 8;
        sm[cr + r * 8][lr] = x[((size_t)(b * CINW + c)) * LPIX + lg * 32 + lr];
    }
    __syncthreads();
    #pragma unroll
    for (int r = 0; r < 4; r++) {
        int lrow = cr + r * 8;
        float v = sm[lr][lrow];
        __half hi = __float2half_rn(v);
        __half lo = __float2half_rn(v - __half2float(hi));
        size_t o = ((size_t)b * XT_ROWS + 128 + lg * 32 + lrow) * CINW + cg * 32 + lr;
        g_xh[o] = hi;
        g_xl[o] = lo;
    }
}

// zero the 128-row pads on both sides of every batch image (vectorized)
__global__ void prep_pad_kernel() {
    int t = blockIdx.x * blockDim.x + threadIdx.x;    // 16*256*16 uint4 rows
    if (t >= BB * 256 * 16) return;
    int c16 = t & 15;
    int pr = (t >> 4) & 255;
    int b = t >> 12;
    int row = (pr < 128) ? pr : (pr + 4096);
    size_t o = ((size_t)b * XT_ROWS + row) * CINW + c16 * 8;
    uint4 z = make_uint4(0, 0, 0, 0);
    *(uint4*)&g_xh[o] = z;
    *(uint4*)&g_xl[o] = z;
}

// weight[o][cin][k] (*1024) -> g_a[(k*2+ch)][o][c] fp16 hi/lo
__global__ void prep_a_kernel(const float* __restrict__ w) {
    int idx = blockIdx.x * blockDim.x + threadIdx.x;  // COUT*CIN*9
    if (idx >= COUTW * CINW * KTAP) return;
    int k = idx % KTAP;
    int cin = (idx / KTAP) % CINW;
    int o = idx / (KTAP * CINW);
    float a = w[idx] * 1024.0f;
    __half hi = __float2half_rn(a);
    __half lo = __float2half_rn(a - __half2float(hi));
    int ch = cin >> 6, c = cin & 63;
    size_t dst = ((size_t)(k * 2 + ch) * 128 + o) * 64 + c;
    g_ah[dst] = hi;
    g_al[dst] = lo;
}

// mterm[o][l] = bias[o] + sum_k mw[o][k]*mask[k][l]
__global__ void prep_mterm_kernel(const float* __restrict__ mask,
                                  const float* __restrict__ mw,
                                  const float* __restrict__ bias) {
    int idx = blockIdx.x * blockDim.x + threadIdx.x;   // 128*4096
    if (idx >= COUTW * LPIX) return;
    int o = idx >> 12, l = idx & 4095;
    float s = bias[o];
    #pragma unroll
    for (int k = 0; k < KTAP; k++)
        s += mw[o * KTAP + k] * mask[k * LPIX + l];
    g_mterm[idx] = s;
}

// ================= main tensor-core kernel (HMMA via mma.sync) =================
__global__ void __launch_bounds__(256, 1)
lmconv_mma_kernel(const float* __restrict__ mask, float* __restrict__ out) {
    extern __shared__ char smem[];
    unsigned sb = smem_u32(smem);
    const int tid = threadIdx.x, wid = tid >> 5, lane = tid & 31;
    const int b = blockIdx.y, l0 = blockIdx.x * TILE_N;
    const int wm = wid >> 1, wn = wid & 1;      // 4 M-warps x 2 N-warps

    unsigned* mS = (unsigned*)(smem + SM_MASK);

    // per-tile mask select words (w-edge wrap folded in)
    for (int j = tid; j < KTAP * TILE_N; j += 256) {
        int k = j >> 7, n = j & 127;
        int l = l0 + n;
        float mv = mask[k * LPIX + l];
        int dx = k % 3 - 1;
        bool m = (mv != 0.0f);
        if (dx == 1  && (l & 63) == 63) m = false;
        if (dx == -1 && (l & 63) == 0)  m = false;
        mS[j] = m ? 0xFFFFFFFFu : 0u;
    }
    __syncthreads();

    float acc[2][8][4];
    #pragma unroll
    for (int im = 0; im < 2; im++)
        #pragma unroll
        for (int jn = 0; jn < 8; jn++)
            #pragma unroll
            for (int q = 0; q < 4; q++) acc[im][jn][q] = 0.0f;

    // lane-invariant ldmatrix address parts
    const unsigned a_l = (unsigned)((wm * 32 + (lane & 15)) * ROWB + ((lane >> 4) * 16));
    const unsigned b_l = (unsigned)((wn * 64 + (lane & 15)) * ROWB + ((lane >> 4) * 16));

    // ---- staging lambda (LDG 16B -> masked -> STS 16B, padded rows) ----
    auto load_stage = [&](int i) {
        char* buf = smem + SM_BUF + (i & 1) * STAGE_BYTES;
        int k = i >> 1, ch = i & 1;
        // A: compact [o][64] -> padded rows
        {
            const uint4* sah = (const uint4*)(g_ah + (size_t)(k * 2 + ch) * 128 * 64);
            const uint4* sal = (const uint4*)(g_al + (size_t)(k * 2 + ch) * 128 * 64);
            #pragma unroll
            for (int j = tid; j < 1024; j += 256) {
                int o = j >> 3, c16 = j & 7;
                unsigned doff = o * ROWB + c16 * 16;
                *(uint4*)(buf + OFF_AH + doff) = sah[j];
                *(uint4*)(buf + OFF_AL + doff) = sal[j];
            }
        }
        // B: row-gather from transposed x with mask AND
        {
            int dlt = (k / 3 - 1) * 64 + (k % 3 - 1);
            size_t base = ((size_t)(b * XT_ROWS + 128 + l0 + dlt)) * CINW + ch * 64;
            const unsigned* mrow = mS + k * TILE_N;
            #pragma unroll
            for (int j = tid; j < 1024; j += 256) {
                int n = j >> 3, c16 = j & 7;
                unsigned m = mrow[n];
                uint4 vh = *(const uint4*)(g_xh + base + (size_t)n * CINW + c16 * 8);
                uint4 vl = *(const uint4*)(g_xl + base + (size_t)n * CINW + c16 * 8);
                vh.x &= m; vh.y &= m; vh.z &= m; vh.w &= m;
                vl.x &= m; vl.y &= m; vl.z &= m; vl.w &= m;
                unsigned doff = n * ROWB + c16 * 16;
                *(uint4*)(buf + OFF_BH + doff) = vh;
                *(uint4*)(buf + OFF_BL + doff) = vl;
            }
        }
    };

    load_stage(0);
    __syncthreads();

    #pragma unroll 1
    for (int i = 0; i < 2 * KTAP; i++) {
        if (i + 1 < 2 * KTAP) load_stage(i + 1);

        unsigned base = sb + SM_BUF + (unsigned)((i & 1) * STAGE_BYTES);
        #pragma unroll
        for (int ks = 0; ks < 4; ks++) {
            unsigned co = ks * 32;                 // 16 halfs per k-step
            unsigned ah[2][4], al[2][4], bh[4][4], bl[4][4];
            ldsm4(ah[0], base + OFF_AH + a_l + co);
            ldsm4(ah[1], base + OFF_AH + a_l + 16 * ROWB + co);
            ldsm4(al[0], base + OFF_AL + a_l + co);
            ldsm4(al[1], base + OFF_AL + a_l + 16 * ROWB + co);
            #pragma unroll
            for (int nb = 0; nb < 4; nb++) {
                ldsm4(bh[nb], base + OFF_BH + b_l + nb * (16 * ROWB) + co);
                ldsm4(bl[nb], base + OFF_BL + b_l + nb * (16 * ROWB) + co);
            }
            #pragma unroll
            for (int im = 0; im < 2; im++) {
                #pragma unroll
                for (int nb = 0; nb < 4; nb++) {
                    mma16816(acc[im][2 * nb + 0], ah[im], bh[nb][0], bh[nb][2]);
                    mma16816(acc[im][2 * nb + 1], ah[im], bh[nb][1], bh[nb][3]);
                    mma16816(acc[im][2 * nb + 0], ah[im], bl[nb][0], bl[nb][2]);
                    mma16816(acc[im][2 * nb + 1], ah[im], bl[nb][1], bl[nb][3]);
                    mma16816(acc[im][2 * nb + 0], al[im], bh[nb][0], bh[nb][2]);
                    mma16816(acc[im][2 * nb + 1], al[im], bh[nb][1], bh[nb][3]);
                }
            }
        }
        __syncthreads();
    }

    // ---- epilogue: unscale (w was *1024), add mterm, store float2 ----
    const float INV = 1.0f / 1024.0f;
    #pragma unroll
    for (int im = 0; im < 2; im++) {
        #pragma unroll
        for (int jn = 0; jn < 8; jn++) {
            int row0 = wm * 32 + im * 16 + (lane >> 2);
            int col = wn * 64 + jn * 8 + (lane & 3) * 2;
            int l = l0 + col;
            {
                const float2 mt = *(const float2*)&g_mterm[(size_t)row0 * LPIX + l];
                float2 v;
                v.x = acc[im][jn][0] * INV + mt.x;
                v.y = acc[im][jn][1] * INV + mt.y;
                *(float2*)&out[((size_t)(b * COUTW + row0)) * LPIX + l] = v;
            }
            {
                int row1 = row0 + 8;
                const float2 mt = *(const float2*)&g_mterm[(size_t)row1 * LPIX + l];
                float2 v;
                v.x = acc[im][jn][2] * INV + mt.x;
                v.y = acc[im][jn][3] * INV + mt.y;
                *(float2*)&out[((size_t)(b * COUTW + row1)) * LPIX + l] = v;
            }
        }
    }
}

// ================= launch =================
extern "C" void kernel_launch(void* const* d_in, const int* in_sizes, int n_in,
                              void* d_out, int out_size) {
    const float* x    = (const float*)d_in[0];   // (16,128,64,64)
    const float* mask = (const float*)d_in[1];   // (1,9,4096)
    const float* w    = (const float*)d_in[2];   // (128,128,3,3)
    const float* mw   = (const float*)d_in[3];   // (128,3,3)
    const float* bias = (const float*)d_in[4];   // (128,)
    float* out = (float*)d_out;                  // (16,128,64,64)

    cudaFuncSetAttribute(lmconv_mma_kernel,
                         cudaFuncAttributeMaxDynamicSharedMemorySize, SMEM_TOTAL);

    prep_x_kernel<<<dim3(128, 4, 16), 256>>>(x);
    prep_pad_kernel<<<(BB * 256 * 16 + 255) / 256, 256>>>();
    prep_a_kernel<<<(COUTW * CINW * KTAP + 255) / 256, 256>>>(w);
    prep_mterm_kernel<<<(COUTW * LPIX + 255) / 256, 256>>>(mask, mw, bias);

    lmconv_mma_kernel<<<dim3(NTILES, BB), 256, SMEM_TOTAL>>>(mask, out);
}

// round 6
// speedup vs baseline: 3.4453x; 1.6665x over previous
#include <cuda_runtime.h>
#include <cuda_fp16.h>

#define BB      16
#define CINW    128
#define COUTW   128
#define LPIX    4096
#define KTAP    9
#define XT_ROWS 4352            // 128 zero-pad + 4096 + 128 zero-pad
#define TILE_N  128
#define NTILES  32              // 4096/128

// smem stage: rows padded to 72 halfs (144B = 16*9) -> 16B-aligned, conflict-free ldmatrix
#define ROWB    144
#define TILEB   (128 * ROWB)    // 18432
#define OFF_A   0
#define OFF_BH  (1 * TILEB)
#define OFF_BL  (2 * TILEB)
#define STAGE_BYTES (3 * TILEB) // 55296
#define SM_MASK 0               // 9*128 u32 = 4608
#define SM_BUF  4608
#define SMEM_TOTAL (SM_BUF + 2 * STAGE_BYTES)   // 115200 -> 2 CTAs/SM (230400 <= 228KB)

// ---- global scratch (__device__ arrays: allocation-free rule) ----
__device__ __align__(16) __half g_xh[(size_t)BB * XT_ROWS * CINW];
__device__ __align__(16) __half g_xl[(size_t)BB * XT_ROWS * CINW];
__device__ __align__(16) __half g_aw[KTAP * 2 * 128 * 64];   // [(k,ch)][o][c] compact fp16
__device__ __align__(16) float  g_mterm[(size_t)COUTW * LPIX];

// ================= PTX helpers (baseline ISA) =================
__device__ __forceinline__ unsigned smem_u32(const void* p) {
    unsigned a;
    asm("{ .reg .u64 t; cvta.to.shared.u64 t, %1; cvt.u32.u64 %0, t; }" : "=r"(a) : "l"(p));
    return a;
}
__device__ __forceinline__ void cp16(unsigned dst, const void* src) {
    asm volatile("cp.async.cg.shared.global [%0], [%1], 16;" :: "r"(dst), "l"(src) : "memory");
}
__device__ __forceinline__ void cp_commit() {
    asm volatile("cp.async.commit_group;" ::: "memory");
}
template <int N> __device__ __forceinline__ void cp_wait() {
    asm volatile("cp.async.wait_group %0;" :: "n"(N) : "memory");
}
__device__ __forceinline__ void ldsm4(unsigned* r, unsigned addr) {
    asm volatile("ldmatrix.sync.aligned.m8n8.x4.shared.b16 {%0,%1,%2,%3}, [%4];"
                 : "=r"(r[0]), "=r"(r[1]), "=r"(r[2]), "=r"(r[3]) : "r"(addr));
}
__device__ __forceinline__ void mma16816(float* c, const unsigned* a,
                                         unsigned b0, unsigned b1) {
    asm volatile(
        "mma.sync.aligned.m16n8k16.row.col.f32.f16.f16.f32 "
        "{%0,%1,%2,%3}, {%4,%5,%6,%7}, {%8,%9}, {%0,%1,%2,%3};"
        : "+f"(c[0]), "+f"(c[1]), "+f"(c[2]), "+f"(c[3])
        : "r"(a[0]), "r"(a[1]), "r"(a[2]), "r"(a[3]), "r"(b0), "r"(b1));
}

// ================= prep kernels =================
// x[b][c][l] fp32 -> x_t[b][128+l][c] fp16 hi/lo via smem tile transpose
__global__ void prep_x_kernel(const float* __restrict__ x) {
    __shared__ float sm[32][33];
    int b = blockIdx.z, cg = blockIdx.y, lg = blockIdx.x;
    int tid = threadIdx.x;
    int lr = tid & 31, cr = tid >> 5;
    #pragma unroll
    for (int r = 0; r < 4; r++) {
        int c = cg * 32 + cr + r * 8;
        sm[cr + r * 8][lr] = x[((size_t)(b * CINW + c)) * LPIX + lg * 32 + lr];
    }
    __syncthreads();
    #pragma unroll
    for (int r = 0; r < 4; r++) {
        int lrow = cr + r * 8;
        float v = sm[lr][lrow];
        __half hi = __float2half_rn(v);
        __half lo = __float2half_rn(v - __half2float(hi));
        size_t o = ((size_t)b * XT_ROWS + 128 + lg * 32 + lrow) * CINW + cg * 32 + lr;
        g_xh[o] = hi;
        g_xl[o] = lo;
    }
}

// zero the 128-row pads on both sides of every batch image (vectorized)
__global__ void prep_pad_kernel() {
    int t = blockIdx.x * blockDim.x + threadIdx.x;    // 16*256*16 uint4 rows
    if (t >= BB * 256 * 16) return;
    int c16 = t & 15;
    int pr = (t >> 4) & 255;
    int b = t >> 12;
    int row = (pr < 128) ? pr : (pr + 4096);
    size_t o = ((size_t)b * XT_ROWS + row) * CINW + c16 * 8;
    uint4 z = make_uint4(0, 0, 0, 0);
    *(uint4*)&g_xh[o] = z;
    *(uint4*)&g_xl[o] = z;
}

// weight[o][cin][k] -> g_aw[(k*2+ch)][o][c] fp16 (w stays single fp16)
__global__ void prep_a_kernel(const float* __restrict__ w) {
    int idx = blockIdx.x * blockDim.x + threadIdx.x;  // COUT*CIN*9
    if (idx >= COUTW * CINW * KTAP) return;
    int k = idx % KTAP;
    int cin = (idx / KTAP) % CINW;
    int o = idx / (KTAP * CINW);
    int ch = cin >> 6, c = cin & 63;
    g_aw[((size_t)(k * 2 + ch) * 128 + o) * 64 + c] = __float2half_rn(w[idx]);
}

// mterm[o][l] = bias[o] + sum_k mw[o][k]*mask[k][l]
__global__ void prep_mterm_kernel(const float* __restrict__ mask,
                                  const float* __restrict__ mw,
                                  const float* __restrict__ bias) {
    int idx = blockIdx.x * blockDim.x + threadIdx.x;   // 128*4096
    if (idx >= COUTW * LPIX) return;
    int o = idx >> 12, l = idx & 4095;
    float s = bias[o];
    #pragma unroll
    for (int k = 0; k < KTAP; k++)
        s += mw[o * KTAP + k] * mask[k * LPIX + l];
    g_mterm[idx] = s;
}

// ================= main tensor-core kernel =================
__global__ void __launch_bounds__(256, 2)
lmconv_mma_kernel(const float* __restrict__ mask, float* __restrict__ out) {
    extern __shared__ char smem[];
    unsigned sb = smem_u32(smem);
    const int tid = threadIdx.x, wid = tid >> 5, lane = tid & 31;
    const int b = blockIdx.y, l0 = blockIdx.x * TILE_N;
    const int wm = wid >> 1, wn = wid & 1;      // 4 M-warps x 2 N-warps

    unsigned* mS = (unsigned*)(smem + SM_MASK);

    // per-tile mask select words (w-edge wrap folded in)
    for (int j = tid; j < KTAP * TILE_N; j += 256) {
        int k = j >> 7, n = j & 127;
        int l = l0 + n;
        float mv = mask[k * LPIX + l];
        int dx = k % 3 - 1;
        bool m = (mv != 0.0f);
        if (dx == 1  && (l & 63) == 63) m = false;
        if (dx == -1 && (l & 63) == 0)  m = false;
        mS[j] = m ? 0xFFFFFFFFu : 0u;
    }

    // ---- async staging: pure cp.async, no transform (mask applied in regs) ----
    auto issue_stage = [&](int i) {
        unsigned buf = sb + SM_BUF + (unsigned)((i & 1) * STAGE_BYTES);
        int k = i >> 1, ch = i & 1;
        // A: compact [o][64] -> padded rows
        const char* srcA = (const char*)(g_aw + (size_t)(k * 2 + ch) * 128 * 64);
        #pragma unroll
        for (int j = tid; j < 1024; j += 256) {
            int o = j >> 3, c16 = j & 7;
            cp16(buf + OFF_A + o * ROWB + c16 * 16, srcA + j * 16);
        }
        // B: shifted rows of transposed x (hi & lo), unmasked
        int dlt = (k / 3 - 1) * 64 + (k % 3 - 1);
        size_t base = ((size_t)(b * XT_ROWS + 128 + l0 + dlt)) * CINW + ch * 64;
        #pragma unroll
        for (int j = tid; j < 1024; j += 256) {
            int n = j >> 3, c16 = j & 7;
            unsigned doff = n * ROWB + c16 * 16;
            size_t soff = base + (size_t)n * CINW + c16 * 8;
            cp16(buf + OFF_BH + doff, g_xh + soff);
            cp16(buf + OFF_BL + doff, g_xl + soff);
        }
        cp_commit();
    };

    float acc[2][8][4];
    #pragma unroll
    for (int im = 0; im < 2; im++)
        #pragma unroll
        for (int jn = 0; jn < 8; jn++)
            #pragma unroll
            for (int q = 0; q < 4; q++) acc[im][jn][q] = 0.0f;

    // lane-invariant ldmatrix address parts
    const unsigned a_l = (unsigned)((wm * 32 + (lane & 15)) * ROWB + ((lane >> 4) * 16));
    const unsigned b_l = (unsigned)((wn * 64 + (lane & 15)) * ROWB + ((lane >> 4) * 16));
    const int mrow = lane >> 2;                  // fragment row within 8-row block

    issue_stage(0);
    __syncthreads();                             // mask words ready (also orders mS)

    #pragma unroll 1
    for (int i = 0; i < 2 * KTAP; i++) {
        if (i + 1 < 2 * KTAP) { issue_stage(i + 1); cp_wait<1>(); }
        else                  { cp_wait<0>(); }
        __syncthreads();                         // stage i visible to all warps

        unsigned base = sb + SM_BUF + (unsigned)((i & 1) * STAGE_BYTES);
        const int k = i >> 1;

        // per-warp mask words for this tap (row-granular, fragment-mapped)
        unsigned mw0[4], mw1[4];
        #pragma unroll
        for (int nb = 0; nb < 4; nb++) {
            mw0[nb] = mS[k * TILE_N + wn * 64 + nb * 16 + mrow];
            mw1[nb] = mS[k * TILE_N + wn * 64 + nb * 16 + 8 + mrow];
        }

        #pragma unroll
        for (int ks = 0; ks < 4; ks++) {
            unsigned co = ks * 32;               // 16 halfs per k-step
            unsigned a[2][4];
            ldsm4(a[0], base + OFF_A + a_l + co);
            ldsm4(a[1], base + OFF_A + a_l + 16 * ROWB + co);
            #pragma unroll
            for (int nb = 0; nb < 4; nb++) {
                unsigned bh[4], bl[4];
                unsigned boff = b_l + nb * (16 * ROWB) + co;
                ldsm4(bh, base + OFF_BH + boff);
                ldsm4(bl, base + OFF_BL + boff);
                bh[0] &= mw0[nb]; bh[2] &= mw0[nb];
                bh[1] &= mw1[nb]; bh[3] &= mw1[nb];
                bl[0] &= mw0[nb]; bl[2] &= mw0[nb];
                bl[1] &= mw1[nb]; bl[3] &= mw1[nb];
                #pragma unroll
                for (int im = 0; im < 2; im++) {
                    mma16816(acc[im][2 * nb + 0], a[im], bh[0], bh[2]);
                    mma16816(acc[im][2 * nb + 1], a[im], bh[1], bh[3]);
                    mma16816(acc[im][2 * nb + 0], a[im], bl[0], bl[2]);
                    mma16816(acc[im][2 * nb + 1], a[im], bl[1], bl[3]);
                }
            }
        }
        __syncthreads();                         // all reads done before buf reuse
    }

    // ---- epilogue: add mterm, store float2 ----
    #pragma unroll
    for (int im = 0; im < 2; im++) {
        #pragma unroll
        for (int jn = 0; jn < 8; jn++) {
            int row0 = wm * 32 + im * 16 + (lane >> 2);
            int col = wn * 64 + jn * 8 + (lane & 3) * 2;
            int l = l0 + col;
            {
                const float2 mt = *(const float2*)&g_mterm[(size_t)row0 * LPIX + l];
                float2 v;
                v.x = acc[im][jn][0] + mt.x;
                v.y = acc[im][jn][1] + mt.y;
                *(float2*)&out[((size_t)(b * COUTW + row0)) * LPIX + l] = v;
            }
            {
                int row1 = row0 + 8;
                const float2 mt = *(const float2*)&g_mterm[(size_t)row1 * LPIX + l];
                float2 v;
                v.x = acc[im][jn][2] + mt.x;
                v.y = acc[im][jn][3] + mt.y;
                *(float2*)&out[((size_t)(b * COUTW + row1)) * LPIX + l] = v;
            }
        }
    }
}

// ================= launch =================
extern "C" void kernel_launch(void* const* d_in, const int* in_sizes, int n_in,
                              void* d_out, int out_size) {
    const float* x    = (const float*)d_in[0];   // (16,128,64,64)
    const float* mask = (const float*)d_in[1];   // (1,9,4096)
    const float* w    = (const float*)d_in[2];   // (128,128,3,3)
    const float* mw   = (const float*)d_in[3];   // (128,3,3)
    const float* bias = (const float*)d_in[4];   // (128,)
    float* out = (float*)d_out;                  // (16,128,64,64)

    cudaFuncSetAttribute(lmconv_mma_kernel,
                         cudaFuncAttributeMaxDynamicSharedMemorySize, SMEM_TOTAL);

    prep_x_kernel<<<dim3(128, 4, 16), 256>>>(x);
    prep_pad_kernel<<<(BB * 256 * 16 + 255) / 256, 256>>>();
    prep_a_kernel<<<(COUTW * CINW * KTAP + 255) / 256, 256>>>(w);
    prep_mterm_kernel<<<(COUTW * LPIX + 255) / 256, 256>>>(mask, mw, bias);

    lmconv_mma_kernel<<<dim3(NTILES, BB), 256, SMEM_TOTAL>>>(mask, out);
}

// round 7
// speedup vs baseline: 5.0577x; 1.4680x over previous
#include <cuda_runtime.h>
#include <cuda_fp16.h>

#define BB      16
#define CINW    128
#define COUTW   128
#define LPIX    4096
#define KTAP    9
#define XT_ROWS 4352            // 128 zero-pad + 4096 + 128 zero-pad
#define TILE_N  128
#define NTILES  32              // 4096/128

// smem stage: rows padded to 72 halfs (144B = 16*9) -> 16B-aligned, conflict-free ldmatrix
#define ROWB    144
#define TILEB   (128 * ROWB)    // 18432
#define OFF_A   0
#define OFF_B   (1 * TILEB)
#define STAGE_BYTES (2 * TILEB) // 36864
#define SM_MASK 0               // 9*128 u32 = 4608
#define SM_BUF  4608
#define SMEM_TOTAL (SM_BUF + 2 * STAGE_BYTES)   // 78336 -> 2 CTAs/SM

// ---- global scratch (__device__ arrays: allocation-free rule) ----
__device__ __align__(16) __half g_x[(size_t)BB * XT_ROWS * CINW];     // fp16 x, transposed+padded
__device__ __align__(16) __half g_aw[KTAP * 2 * 128 * 64];            // [(k,ch)][o][c] fp16 w
__device__ __align__(16) float  g_mterm[(size_t)COUTW * LPIX];

// ================= PTX helpers (baseline ISA) =================
__device__ __forceinline__ unsigned smem_u32(const void* p) {
    unsigned a;
    asm("{ .reg .u64 t; cvta.to.shared.u64 t, %1; cvt.u32.u64 %0, t; }" : "=r"(a) : "l"(p));
    return a;
}
__device__ __forceinline__ void cp16(unsigned dst, const void* src) {
    asm volatile("cp.async.cg.shared.global [%0], [%1], 16;" :: "r"(dst), "l"(src) : "memory");
}
__device__ __forceinline__ void cp_commit() {
    asm volatile("cp.async.commit_group;" ::: "memory");
}
template <int N> __device__ __forceinline__ void cp_wait() {
    asm volatile("cp.async.wait_group %0;" :: "n"(N) : "memory");
}
__device__ __forceinline__ void ldsm4(unsigned* r, unsigned addr) {
    asm volatile("ldmatrix.sync.aligned.m8n8.x4.shared.b16 {%0,%1,%2,%3}, [%4];"
                 : "=r"(r[0]), "=r"(r[1]), "=r"(r[2]), "=r"(r[3]) : "r"(addr));
}
__device__ __forceinline__ void mma16816(float* c, const unsigned* a,
                                         unsigned b0, unsigned b1) {
    asm volatile(
        "mma.sync.aligned.m16n8k16.row.col.f32.f16.f16.f32 "
        "{%0,%1,%2,%3}, {%4,%5,%6,%7}, {%8,%9}, {%0,%1,%2,%3};"
        : "+f"(c[0]), "+f"(c[1]), "+f"(c[2]), "+f"(c[3])
        : "r"(a[0]), "r"(a[1]), "r"(a[2]), "r"(a[3]), "r"(b0), "r"(b1));
}

// ================= prep kernels =================
// x[b][c][l] fp32 -> x_t[b][128+l][c] fp16 via smem tile transpose
__global__ void prep_x_kernel(const float* __restrict__ x) {
    __shared__ float sm[32][33];
    int b = blockIdx.z, cg = blockIdx.y, lg = blockIdx.x;
    int tid = threadIdx.x;
    int lr = tid & 31, cr = tid >> 5;
    #pragma unroll
    for (int r = 0; r < 4; r++) {
        int c = cg * 32 + cr + r * 8;
        sm[cr + r * 8][lr] = x[((size_t)(b * CINW + c)) * LPIX + lg * 32 + lr];
    }
    __syncthreads();
    #pragma unroll
    for (int r = 0; r < 4; r++) {
        int lrow = cr + r * 8;
        float v = sm[lr][lrow];
        size_t o = ((size_t)b * XT_ROWS + 128 + lg * 32 + lrow) * CINW + cg * 32 + lr;
        g_x[o] = __float2half_rn(v);
    }
}

// zero the 128-row pads on both sides of every batch image (vectorized)
__global__ void prep_pad_kernel() {
    int t = blockIdx.x * blockDim.x + threadIdx.x;    // 16*256*16 uint4 rows
    if (t >= BB * 256 * 16) return;
    int c16 = t & 15;
    int pr = (t >> 4) & 255;
    int b = t >> 12;
    int row = (pr < 128) ? pr : (pr + 4096);
    *(uint4*)&g_x[((size_t)b * XT_ROWS + row) * CINW + c16 * 8] = make_uint4(0, 0, 0, 0);
}

// weight[o][cin][k] -> g_aw[(k*2+ch)][o][c] fp16
__global__ void prep_a_kernel(const float* __restrict__ w) {
    int idx = blockIdx.x * blockDim.x + threadIdx.x;  // COUT*CIN*9
    if (idx >= COUTW * CINW * KTAP) return;
    int k = idx % KTAP;
    int cin = (idx / KTAP) % CINW;
    int o = idx / (KTAP * CINW);
    int ch = cin >> 6, c = cin & 63;
    g_aw[((size_t)(k * 2 + ch) * 128 + o) * 64 + c] = __float2half_rn(w[idx]);
}

// mterm[o][l] = bias[o] + sum_k mw[o][k]*mask[k][l]
__global__ void prep_mterm_kernel(const float* __restrict__ mask,
                                  const float* __restrict__ mw,
                                  const float* __restrict__ bias) {
    int idx = blockIdx.x * blockDim.x + threadIdx.x;   // 128*4096
    if (idx >= COUTW * LPIX) return;
    int o = idx >> 12, l = idx & 4095;
    float s = bias[o];
    #pragma unroll
    for (int k = 0; k < KTAP; k++)
        s += mw[o * KTAP + k] * mask[k * LPIX + l];
    g_mterm[idx] = s;
}

// ================= main tensor-core kernel =================
__global__ void __launch_bounds__(256, 2)
lmconv_mma_kernel(const float* __restrict__ mask, float* __restrict__ out) {
    extern __shared__ char smem[];
    unsigned sb = smem_u32(smem);
    const int tid = threadIdx.x, wid = tid >> 5, lane = tid & 31;
    const int b = blockIdx.y, l0 = blockIdx.x * TILE_N;
    const int wm = wid >> 1, wn = wid & 1;      // 4 M-warps x 2 N-warps

    unsigned* mS = (unsigned*)(smem + SM_MASK);

    // per-tile mask select words (w-edge wrap folded in)
    for (int j = tid; j < KTAP * TILE_N; j += 256) {
        int k = j >> 7, n = j & 127;
        int l = l0 + n;
        float mv = mask[k * LPIX + l];
        int dx = k % 3 - 1;
        bool m = (mv != 0.0f);
        if (dx == 1  && (l & 63) == 63) m = false;
        if (dx == -1 && (l & 63) == 0)  m = false;
        mS[j] = m ? 0xFFFFFFFFu : 0u;
    }

    // ---- async staging: pure cp.async (mask applied in regs after ldmatrix) ----
    auto issue_stage = [&](int i) {
        unsigned buf = sb + SM_BUF + (unsigned)((i & 1) * STAGE_BYTES);
        int k = i >> 1, ch = i & 1;
        // A: compact [o][64] -> padded rows
        const char* srcA = (const char*)(g_aw + (size_t)(k * 2 + ch) * 128 * 64);
        #pragma unroll
        for (int j = tid; j < 1024; j += 256) {
            int o = j >> 3, c16 = j & 7;
            cp16(buf + OFF_A + o * ROWB + c16 * 16, srcA + j * 16);
        }
        // B: shifted rows of transposed x, unmasked
        int dlt = (k / 3 - 1) * 64 + (k % 3 - 1);
        size_t base = ((size_t)(b * XT_ROWS + 128 + l0 + dlt)) * CINW + ch * 64;
        #pragma unroll
        for (int j = tid; j < 1024; j += 256) {
            int n = j >> 3, c16 = j & 7;
            cp16(buf + OFF_B + n * ROWB + c16 * 16,
                 g_x + base + (size_t)n * CINW + c16 * 8);
        }
        cp_commit();
    };

    float acc[2][8][4];
    #pragma unroll
    for (int im = 0; im < 2; im++)
        #pragma unroll
        for (int jn = 0; jn < 8; jn++)
            #pragma unroll
            for (int q = 0; q < 4; q++) acc[im][jn][q] = 0.0f;

    // lane-invariant ldmatrix address parts
    const unsigned a_l = (unsigned)((wm * 32 + (lane & 15)) * ROWB + ((lane >> 4) * 16));
    const unsigned b_l = (unsigned)((wn * 64 + (lane & 15)) * ROWB + ((lane >> 4) * 16));
    const int mrow = lane >> 2;                  // fragment row within 8-row block

    issue_stage(0);
    __syncthreads();                             // mask words ready (also orders mS)

    #pragma unroll 1
    for (int i = 0; i < 2 * KTAP; i++) {
        if (i + 1 < 2 * KTAP) { issue_stage(i + 1); cp_wait<1>(); }
        else                  { cp_wait<0>(); }
        __syncthreads();                         // stage i visible to all warps

        unsigned base = sb + SM_BUF + (unsigned)((i & 1) * STAGE_BYTES);
        const int k = i >> 1;

        // per-warp mask words for this tap (row-granular, fragment-mapped)
        unsigned mw0[4], mw1[4];
        #pragma unroll
        for (int nb = 0; nb < 4; nb++) {
            mw0[nb] = mS[k * TILE_N + wn * 64 + nb * 16 + mrow];
            mw1[nb] = mS[k * TILE_N + wn * 64 + nb * 16 + 8 + mrow];
        }

        #pragma unroll
        for (int ks = 0; ks < 4; ks++) {
            unsigned co = ks * 32;               // 16 halfs per k-step
            unsigned a[2][4];
            ldsm4(a[0], base + OFF_A + a_l + co);
            ldsm4(a[1], base + OFF_A + a_l + 16 * ROWB + co);
            #pragma unroll
            for (int nb = 0; nb < 4; nb++) {
                unsigned bf[4];
                ldsm4(bf, base + OFF_B + b_l + nb * (16 * ROWB) + co);
                bf[0] &= mw0[nb]; bf[2] &= mw0[nb];
                bf[1] &= mw1[nb]; bf[3] &= mw1[nb];
                #pragma unroll
                for (int im = 0; im < 2; im++) {
                    mma16816(acc[im][2 * nb + 0], a[im], bf[0], bf[2]);
                    mma16816(acc[im][2 * nb + 1], a[im], bf[1], bf[3]);
                }
            }
        }
        __syncthreads();                         // all reads done before buf reuse
    }

    // ---- epilogue: add mterm, store float2 ----
    #pragma unroll
    for (int im = 0; im < 2; im++) {
        #pragma unroll
        for (int jn = 0; jn < 8; jn++) {
            int row0 = wm * 32 + im * 16 + (lane >> 2);
            int col = wn * 64 + jn * 8 + (lane & 3) * 2;
            int l = l0 + col;
            {
                const float2 mt = *(const float2*)&g_mterm[(size_t)row0 * LPIX + l];
                float2 v;
                v.x = acc[im][jn][0] + mt.x;
                v.y = acc[im][jn][1] + mt.y;
                *(float2*)&out[((size_t)(b * COUTW + row0)) * LPIX + l] = v;
            }
            {
                int row1 = row0 + 8;
                const float2 mt = *(const float2*)&g_mterm[(size_t)row1 * LPIX + l];
                float2 v;
                v.x = acc[im][jn][2] + mt.x;
                v.y = acc[im][jn][3] + mt.y;
                *(float2*)&out[((size_t)(b * COUTW + row1)) * LPIX + l] = v;
            }
        }
    }
}

// ================= launch =================
extern "C" void kernel_launch(void* const* d_in, const int* in_sizes, int n_in,
                              void* d_out, int out_size) {
    const float* x    = (const float*)d_in[0];   // (16,128,64,64)
    const float* mask = (const float*)d_in[1];   // (1,9,4096)
    const float* w    = (const float*)d_in[2];   // (128,128,3,3)
    const float* mw   = (const float*)d_in[3];   // (128,3,3)
    const float* bias = (const float*)d_in[4];   // (128,)
    float* out = (float*)d_out;                  // (16,128,64,64)

    cudaFuncSetAttribute(lmconv_mma_kernel,
                         cudaFuncAttributeMaxDynamicSharedMemorySize, SMEM_TOTAL);

    prep_x_kernel<<<dim3(128, 4, 16), 256>>>(x);
    prep_pad_kernel<<<(BB * 256 * 16 + 255) / 256, 256>>>();
    prep_a_kernel<<<(COUTW * CINW * KTAP + 255) / 256, 256>>>(w);
    prep_mterm_kernel<<<(COUTW * LPIX + 255) / 256, 256>>>(mask, mw, bias);

    lmconv_mma_kernel<<<dim3(NTILES, BB), 256, SMEM_TOTAL>>>(mask, out);
}